// round 1
// baseline (speedup 1.0000x reference)
#include <cuda_runtime.h>

#define B_    8
#define NV_   8192
#define E_    32768
#define BLK   256
#define NTILE 512                 // n-columns per block (BLK threads * 2 n each)
#define NTILES (NV_ / NTILE)      // 16
#define NSEG  128
#define ESEG  (E_ / NSEG)         // 256
#define CH    128                 // e-chunk staged in shared
#define PLANE (NV_ * 24)          // 196608 floats per partial plane

// Scratch (device globals: allocation-free kernel_launch)
__device__ float g_M[E_ * 24];                      // M in layout [e][c*8 + b]  (3 MB)
__device__ float g_part[(size_t)NSEG * PLANE];      // per-segment partial sums (100 MB)

// ---------- f32x2 helpers (FFMA2) ----------
__device__ __forceinline__ unsigned long long pack_dup(float x) {
    unsigned long long r;
    asm("mov.b64 %0, {%1, %1};" : "=l"(r) : "f"(x));
    return r;
}
__device__ __forceinline__ void fma2(unsigned long long& d, unsigned long long a, unsigned long long b) {
    asm("fma.rn.f32x2 %0, %1, %2, %0;" : "+l"(d) : "l"(a), "l"(b));
}
__device__ __forceinline__ float2 unpack2(unsigned long long v) {
    float2 f;
    asm("mov.b64 {%0, %1}, %2;" : "=f"(f.x), "=f"(f.y) : "l"(v));
    return f;
}

// ---------- Kernel 1: per-edge XPBD solve ----------
__global__ void edge_kernel(const float* __restrict__ Vp, const float* __restrict__ L,
                            const float* __restrict__ Vw, const float* __restrict__ Vc,
                            const int* __restrict__ Cd, const float* __restrict__ C0,
                            float* __restrict__ Lnew) {
    int e = blockIdx.x * blockDim.x + threadIdx.x;
    if (e >= E_) return;
    int i = Cd[2 * e];
    int j = Cd[2 * e + 1];
    float c0 = C0[e];
    float m[24];
#pragma unroll
    for (int b = 0; b < B_; b++) {
        const float* pi = Vp + ((size_t)b * NV_ + i) * 3;
        const float* pj = Vp + ((size_t)b * NV_ + j) * 3;
        float nx = pi[0] - pj[0];
        float ny = pi[1] - pj[1];
        float nz = pi[2] - pj[2];
        float D = sqrtf(nx * nx + ny * ny + nz * nz);
        float C = D - c0;
        float invD = 1.0f / (D + 1e-8f);
        float A = Vc[b];
        float S = Vw[b * NV_ + i] + Vw[b * NV_ + j];
        if (S == 0.0f) S = __int_as_float(0x7f800000);  // +inf
        float Lbe = L[b * E_ + e];
        float Ld = (-C - A * Lbe) / (S + A);
        Lnew[b * E_ + e] = Lbe + Ld;
        float s = Ld * invD;
        m[0 * 8 + b] = s * nx;
        m[1 * 8 + b] = s * ny;
        m[2 * 8 + b] = s * nz;
    }
#pragma unroll
    for (int k = 0; k < 24; k++) g_M[(size_t)e * 24 + k] = m[k];
}

// ---------- Kernel 2: skinny GEMM, batch-packed f32x2 accumulation ----------
__global__ void __launch_bounds__(BLK, 2) gemm_kernel(const float* __restrict__ Cmtx) {
    int nt = blockIdx.x;
    int seg = blockIdx.y;
    int n0 = nt * NTILE + threadIdx.x * 2;

    __shared__ __align__(16) unsigned long long sh[CH * 12];

    unsigned long long accA[12], accB[12];
#pragma unroll
    for (int k = 0; k < 12; k++) { accA[k] = 0ull; accB[k] = 0ull; }

    size_t ebase0 = (size_t)seg * ESEG;

    for (int ch = 0; ch < ESEG / CH; ch++) {
        size_t ebase = ebase0 + (size_t)ch * CH;
        // Stage CH edges worth of M (CH*24 floats = CH*12 u64) into shared.
        {
            const ulonglong2* src = reinterpret_cast<const ulonglong2*>(g_M + ebase * 24);
            ulonglong2* dst = reinterpret_cast<ulonglong2*>(sh);
#pragma unroll
            for (int r = 0; r < (CH * 12 / 2) / BLK; r++)
                dst[r * BLK + threadIdx.x] = src[r * BLK + threadIdx.x];
        }
        __syncthreads();

        const float* crow = Cmtx + ebase * NV_ + n0;
#pragma unroll 4
        for (int t = 0; t < CH; t++) {
            float2 cv = __ldcs(reinterpret_cast<const float2*>(crow + (size_t)t * NV_));
            unsigned long long cd0 = pack_dup(cv.x);
            unsigned long long cd1 = pack_dup(cv.y);
            const unsigned long long* mrow = sh + t * 12;
            ulonglong2 m01 = *reinterpret_cast<const ulonglong2*>(mrow + 0);
            ulonglong2 m23 = *reinterpret_cast<const ulonglong2*>(mrow + 2);
            ulonglong2 m45 = *reinterpret_cast<const ulonglong2*>(mrow + 4);
            ulonglong2 m67 = *reinterpret_cast<const ulonglong2*>(mrow + 6);
            ulonglong2 m89 = *reinterpret_cast<const ulonglong2*>(mrow + 8);
            ulonglong2 mAB = *reinterpret_cast<const ulonglong2*>(mrow + 10);
            fma2(accA[0], cd0, m01.x);  fma2(accB[0], cd1, m01.x);
            fma2(accA[1], cd0, m01.y);  fma2(accB[1], cd1, m01.y);
            fma2(accA[2], cd0, m23.x);  fma2(accB[2], cd1, m23.x);
            fma2(accA[3], cd0, m23.y);  fma2(accB[3], cd1, m23.y);
            fma2(accA[4], cd0, m45.x);  fma2(accB[4], cd1, m45.x);
            fma2(accA[5], cd0, m45.y);  fma2(accB[5], cd1, m45.y);
            fma2(accA[6], cd0, m67.x);  fma2(accB[6], cd1, m67.x);
            fma2(accA[7], cd0, m67.y);  fma2(accB[7], cd1, m67.y);
            fma2(accA[8], cd0, m89.x);  fma2(accB[8], cd1, m89.x);
            fma2(accA[9], cd0, m89.y);  fma2(accB[9], cd1, m89.y);
            fma2(accA[10], cd0, mAB.x); fma2(accB[10], cd1, mAB.x);
            fma2(accA[11], cd0, mAB.y); fma2(accB[11], cd1, mAB.y);
        }
        __syncthreads();
    }

    // Disjoint partial writes: layout [seg][n*24 + c*8 + b]
    float* outp = g_part + (size_t)seg * PLANE;
#pragma unroll
    for (int k = 0; k < 12; k++) {
        int c = k >> 2;
        int bp = k & 3;
        float2 a = unpack2(accA[k]);
        float2 b2 = unpack2(accB[k]);
        *reinterpret_cast<float2*>(outp + (size_t)n0 * 24 + c * 8 + bp * 2) = a;
        *reinterpret_cast<float2*>(outp + (size_t)(n0 + 1) * 24 + c * 8 + bp * 2) = b2;
    }
}

// ---------- Kernel 3: reduce partials + epilogue ----------
__global__ void final_kernel(const float* __restrict__ Vp, const float* __restrict__ Vw,
                             float* __restrict__ out) {
    int t = blockIdx.x * blockDim.x + threadIdx.x;
    if (t >= PLANE) return;
    int n = t / 24;
    int k = t % 24;
    int c = k >> 3;
    int b = k & 7;
    float s = 0.0f;
#pragma unroll 8
    for (int seg = 0; seg < NSEG; seg++) s += g_part[(size_t)seg * PLANE + t];
    size_t oidx = ((size_t)b * NV_ + n) * 3 + c;
    out[oidx] = Vp[oidx] + Vw[b * NV_ + n] * s;
}

extern "C" void kernel_launch(void* const* d_in, const int* in_sizes, int n_in,
                              void* d_out, int out_size) {
    const float* Vp = (const float*)d_in[0];   // (B, NV, 3)
    const float* L  = (const float*)d_in[1];   // (B, E, 1)
    const float* Vw = (const float*)d_in[2];   // (B, NV, 1)
    const float* Vc = (const float*)d_in[3];   // (B, 1, 1)
    const int*   Cd = (const int*)d_in[4];     // (E, 2)
    const float* C0 = (const float*)d_in[5];   // (E, 1)
    const float* Cm = (const float*)d_in[6];   // (E, NV)

    float* out = (float*)d_out;
    float* Lnew = out + (size_t)B_ * NV_ * 3;  // second tuple element

    edge_kernel<<<E_ / 256, 256>>>(Vp, L, Vw, Vc, Cd, C0, Lnew);
    gemm_kernel<<<dim3(NTILES, NSEG), BLK>>>(Cm);
    final_kernel<<<(PLANE + 255) / 256, 256>>>(Vp, Vw, out);
}

// round 5
// speedup vs baseline: 1.1837x; 1.1837x over previous
#include <cuda_runtime.h>
#include <cstdint>

#define B_      8
#define NV_     8192
#define E_      32768
#define KSPLIT  16
#define KRANGE  (E_ / KSPLIT)     // 2048
#define CHK     128               // A-chunk (e) staged in smem
#define NCHUNK  (KRANGE / CHK)    // 16
#define VT      256               // vertices per CTA
#define NVT     (NV_ / VT)        // 32
#define SAPAD   132               // smem A row stride (floats): (4*cb + k) % 32 distinct

// Scratch (device globals: allocation-free kernel_launch)
__device__ float g_Mt[24 * E_];                   // M transposed: [cb][e]  (3 MB)
__device__ float g_part[KSPLIT * 24 * NV_];       // K-split partials [ks][cb][n] (12.6 MB)

// ---------------- Kernel 1: per-edge XPBD solve, thread per (b, e) ----------------
__global__ void edge_kernel(const float* __restrict__ Vp, const float* __restrict__ L,
                            const float* __restrict__ Vw, const float* __restrict__ Vc,
                            const int* __restrict__ Cd, const float* __restrict__ C0,
                            float* __restrict__ Lnew) {
    int idx = blockIdx.x * blockDim.x + threadIdx.x;   // b*E_ + e
    int b = idx >> 15;            // E_ = 2^15
    int e = idx & (E_ - 1);
    int i = Cd[2 * e];
    int j = Cd[2 * e + 1];
    float c0 = C0[e];
    const float* pi = Vp + ((size_t)b * NV_ + i) * 3;
    const float* pj = Vp + ((size_t)b * NV_ + j) * 3;
    float nx = pi[0] - pj[0];
    float ny = pi[1] - pj[1];
    float nz = pi[2] - pj[2];
    float D = sqrtf(nx * nx + ny * ny + nz * nz);
    float C = D - c0;
    float invD = 1.0f / (D + 1e-8f);
    float A = Vc[b];
    float S = Vw[b * NV_ + i] + Vw[b * NV_ + j];
    if (S == 0.0f) S = __int_as_float(0x7f800000);
    float Lbe = L[b * E_ + e];
    float Ld = (-C - A * Lbe) / (S + A);
    Lnew[b * E_ + e] = Lbe + Ld;
    float s = Ld * invD;
    g_Mt[(0 * 8 + b) * E_ + e] = s * nx;
    g_Mt[(1 * 8 + b) * E_ + e] = s * ny;
    g_Mt[(2 * 8 + b) * E_ + e] = s * nz;
}

// ---------------- tf32 HMMA helper ----------------
__device__ __forceinline__ void mma_tf32(float* c, uint32_t a0, uint32_t a1, uint32_t a2,
                                         uint32_t a3, uint32_t b0, uint32_t b1) {
    asm volatile(
        "mma.sync.aligned.m16n8k8.row.col.f32.tf32.tf32.f32 "
        "{%0,%1,%2,%3}, {%4,%5,%6,%7}, {%8,%9}, {%0,%1,%2,%3};"
        : "+f"(c[0]), "+f"(c[1]), "+f"(c[2]), "+f"(c[3])
        : "r"(a0), "r"(a1), "r"(a2), "r"(a3), "r"(b0), "r"(b1));
}

// ---------------- Kernel 2: tf32 HMMA GEMM ----------------
// out[m=cb (24->32 padded)][n=vertex] += A[m][k=e] * B[k][n]
//   A = g_Mt (smem-staged per 128-e chunk), B = Cmtx streamed global->regs
__global__ void __launch_bounds__(256) gemm_kernel(const float* __restrict__ Cmtx) {
    __shared__ float sA[32 * SAPAD];

    int tid = threadIdx.x;
    int wid = tid >> 5;
    int lane = tid & 31;
    int vt = blockIdx.x;
    int ks = blockIdx.y;
    int vw = vt * VT + wid * 32;                 // this warp's 32 vertices
    int ebase0 = ks * KRANGE;

    // zero A pad rows 24..31 once (never written again)
    for (int f = tid; f < 8 * SAPAD; f += 256) sA[24 * SAPAD + f] = 0.0f;

    float acc[2][4][4];
#pragma unroll
    for (int mt = 0; mt < 2; mt++)
#pragma unroll
        for (int nt = 0; nt < 4; nt++)
#pragma unroll
            for (int k = 0; k < 4; k++) acc[mt][nt][k] = 0.0f;

    int kq = lane & 3;     // k within quad
    int g  = lane >> 2;    // group id

#pragma unroll 1
    for (int chunk = 0; chunk < NCHUNK; chunk++) {
        int eb = ebase0 + chunk * CHK;
        __syncthreads();
        // stage A chunk: rows 0..23, CHK e-columns
#pragma unroll
        for (int it = 0; it < 3; it++) {
            int f = tid + it * 256;              // 0..767
            int row = f >> 5, q = f & 31;
            float4 v = *reinterpret_cast<const float4*>(g_Mt + (size_t)row * E_ + eb + q * 4);
            *reinterpret_cast<float4*>(sA + row * SAPAD + q * 4) = v;
        }
        __syncthreads();

#pragma unroll
        for (int s = 0; s < CHK / 8; s++) {
            // B fragments straight from global: b0 k=kq, b1 k=kq+4, col n = g
            const float* bp = Cmtx + (size_t)(eb + s * 8 + kq) * NV_ + vw + g;
            uint32_t b0[4], b1[4];
#pragma unroll
            for (int nt = 0; nt < 4; nt++) {
                b0[nt] = __float_as_uint(__ldcs(bp + nt * 8));
                b1[nt] = __float_as_uint(__ldcs(bp + 4 * NV_ + nt * 8));
            }
            // A fragments from smem
            int koff = s * 8 + kq;
            uint32_t a[2][4];
#pragma unroll
            for (int mt = 0; mt < 2; mt++) {
                const float* ap = sA + (mt * 16 + g) * SAPAD + koff;
                a[mt][0] = __float_as_uint(ap[0]);
                a[mt][1] = __float_as_uint(ap[8 * SAPAD]);
                a[mt][2] = __float_as_uint(ap[4]);
                a[mt][3] = __float_as_uint(ap[8 * SAPAD + 4]);
            }
#pragma unroll
            for (int mt = 0; mt < 2; mt++)
#pragma unroll
                for (int nt = 0; nt < 4; nt++)
                    mma_tf32(acc[mt][nt], a[mt][0], a[mt][1], a[mt][2], a[mt][3],
                             b0[nt], b1[nt]);
        }
    }

    // store partials: g_part[ks][cb][v], cb rows: mt0 -> g, g+8 ; mt1 -> 16+g (24..31 dropped)
    float* pb = g_part + (size_t)ks * 24 * NV_;
    int q2 = (lane & 3) * 2;
#pragma unroll
    for (int nt = 0; nt < 4; nt++) {
        int v = vw + nt * 8 + q2;
        *reinterpret_cast<float2*>(pb + (size_t)g * NV_ + v) =
            make_float2(acc[0][nt][0], acc[0][nt][1]);
        *reinterpret_cast<float2*>(pb + (size_t)(g + 8) * NV_ + v) =
            make_float2(acc[0][nt][2], acc[0][nt][3]);
        *reinterpret_cast<float2*>(pb + (size_t)(g + 16) * NV_ + v) =
            make_float2(acc[1][nt][0], acc[1][nt][1]);
    }
}

// ---------------- Kernel 3: reduce K-split partials + epilogue ----------------
__global__ void final_kernel(const float* __restrict__ Vp, const float* __restrict__ Vw,
                             float* __restrict__ out) {
    int t = blockIdx.x * blockDim.x + threadIdx.x;   // cb*NV_ + n
    if (t >= 24 * NV_) return;
    int cb = t >> 13;            // NV_ = 2^13
    int n = t & (NV_ - 1);
    float s = 0.0f;
#pragma unroll
    for (int k = 0; k < KSPLIT; k++) s += g_part[(size_t)k * 24 * NV_ + t];
    int c = cb >> 3, b = cb & 7;
    size_t oidx = ((size_t)b * NV_ + n) * 3 + c;
    out[oidx] = Vp[oidx] + Vw[b * NV_ + n] * s;
}

extern "C" void kernel_launch(void* const* d_in, const int* in_sizes, int n_in,
                              void* d_out, int out_size) {
    const float* Vp = (const float*)d_in[0];   // (B, NV, 3)
    const float* L  = (const float*)d_in[1];   // (B, E, 1)
    const float* Vw = (const float*)d_in[2];   // (B, NV, 1)
    const float* Vc = (const float*)d_in[3];   // (B, 1, 1)
    const int*   Cd = (const int*)d_in[4];     // (E, 2)
    const float* C0 = (const float*)d_in[5];   // (E, 1)
    const float* Cm = (const float*)d_in[6];   // (E, NV)

    float* out = (float*)d_out;
    float* Lnew = out + (size_t)B_ * NV_ * 3;

    edge_kernel<<<(B_ * E_) / 256, 256>>>(Vp, L, Vw, Vc, Cd, C0, Lnew);
    gemm_kernel<<<dim3(NVT, KSPLIT), 256>>>(Cm);
    final_kernel<<<(24 * NV_ + 255) / 256, 256>>>(Vp, Vw, out);
}